// round 2
// baseline (speedup 1.0000x reference)
#include <cuda_runtime.h>
#include <math.h>

#define BB 2
#define NN 512
#define SS 384
#define ZC 128
#define HH 12
#define CC 16
#define PQn 4
#define PVn 8
#define HC 192      /* H*C   */
#define HPQ3 144    /* H*PQ*3*/
#define HPV3 288    /* H*PV*3*/
#define CATW 2112   /* H*(C+4PV+Z) */
#define PROJ_W 1152

#define WLC  0.5773502691896258f     /* sqrt(1/3) */
#define COEF 0.06804138174397717f    /* wL*wC/2, wC=sqrt(2/(9*PQ)) */

__device__ __align__(16) float g_q [BB*NN*HC];
__device__ __align__(16) float g_k [BB*NN*HC];
__device__ __align__(16) float g_v [BB*NN*HC];
__device__ __align__(16) float g_qp[BB*NN*HPQ3];
__device__ __align__(16) float g_kp[BB*NN*HPQ3];
__device__ __align__(16) float g_vp[BB*NN*HPV3];
__device__ __align__(16) float g_qq[BB*NN*HH];
__device__ __align__(16) float g_kk[BB*NN*HH];
__device__ __align__(16) float g_cat[BB*NN*CATW];
__device__ __align__(16) float g_wcat[SS*PROJ_W];   // packed projection weights
__device__ __align__(16) float g_proj[BB*NN*PROJ_W];

__device__ __forceinline__ float dot4(float4 a, float4 b) {
    return a.x*b.x + a.y*b.y + a.z*b.z + a.w*b.w;
}

// ---------------------------------------------------------------------------
// Kernel 0: pack Wq|Wk|Wv|Wqp|Wkp|Wvp into g_wcat[384][1152]
// ---------------------------------------------------------------------------
__global__ __launch_bounds__(256) void k_pack(
    const float* __restrict__ Wq, const float* __restrict__ Wk, const float* __restrict__ Wv,
    const float* __restrict__ Wqp, const float* __restrict__ Wkp, const float* __restrict__ Wvp)
{
    const int idx = blockIdx.x*256 + threadIdx.x;
    const int si = idx / PROJ_W, col = idx % PROJ_W;
    float v;
    if      (col < 192) v = Wq [si*192 + col];
    else if (col < 384) v = Wk [si*192 + col - 192];
    else if (col < 576) v = Wv [si*192 + col - 384];
    else if (col < 720) v = Wqp[si*144 + col - 576];
    else if (col < 864) v = Wkp[si*144 + col - 720];
    else                v = Wvp[si*288 + col - 864];
    g_wcat[idx] = v;
}

// ---------------------------------------------------------------------------
// Generic tiled fp32 GEMM: C[M,N] = A[M,lda] @ B[K,ldb], 256 threads.
// BM x BN tile, BK=32, each thread TM x TN outputs. (BM/TM)*(BN/TN)==256.
// ---------------------------------------------------------------------------
template<int BM, int BN, int TM, int TN>
__global__ __launch_bounds__(256) void k_gemm(
    const float* __restrict__ A, int lda,
    const float* __restrict__ B, int ldb,
    float* __restrict__ C, int ldc, int K)
{
    constexpr int BK = 32;
    __shared__ float As[BK][BM + 1];
    __shared__ __align__(16) float Bs[BK][BN];
    const int tid = threadIdx.x;
    const int ncols = BN / TN;               // thread cols
    const int tr = tid / ncols;              // thread row
    const int tc = tid % ncols;              // thread col
    const int m0 = blockIdx.y * BM;
    const int n0 = blockIdx.x * BN;

    float acc[TM][TN];
    #pragma unroll
    for (int i = 0; i < TM; i++)
        #pragma unroll
        for (int j = 0; j < TN; j++) acc[i][j] = 0.f;

    for (int k0 = 0; k0 < K; k0 += BK) {
        #pragma unroll
        for (int r = 0; r < (BM*BK)/256; r++) {
            const int idx = tid + r*256;
            const int m = idx / BK, kk = idx % BK;
            As[kk][m] = A[(m0 + m)*lda + k0 + kk];
        }
        #pragma unroll
        for (int r = 0; r < (BN*BK)/256; r++) {
            const int idx = tid + r*256;
            const int kk = idx / BN, n = idx % BN;
            Bs[kk][n] = B[(k0 + kk)*ldb + n0 + n];
        }
        __syncthreads();
        #pragma unroll
        for (int kk = 0; kk < BK; kk++) {
            float a[TM];
            #pragma unroll
            for (int i = 0; i < TM; i++) a[i] = As[kk][tr*TM + i];
            const float4 b4 = *(const float4*)&Bs[kk][tc*TN];
            #pragma unroll
            for (int i = 0; i < TM; i++) {
                acc[i][0] = fmaf(a[i], b4.x, acc[i][0]);
                acc[i][1] = fmaf(a[i], b4.y, acc[i][1]);
                acc[i][2] = fmaf(a[i], b4.z, acc[i][2]);
                acc[i][3] = fmaf(a[i], b4.w, acc[i][3]);
            }
        }
        __syncthreads();
    }
    #pragma unroll
    for (int i = 0; i < TM; i++) {
        float4 v = make_float4(acc[i][0], acc[i][1], acc[i][2], acc[i][3]);
        *(float4*)&C[(m0 + tr*TM + i)*ldc + n0 + tc*TN] = v;
    }
}

// ---------------------------------------------------------------------------
// Kernel: post-projection epilogue. One block per (b,n) residue.
// ---------------------------------------------------------------------------
__global__ __launch_bounds__(128) void k_projpost(
    const float* __restrict__ R, const float* __restrict__ t)
{
    __shared__ float qq_sh[HH], kk_sh[HH];
    __shared__ float Rl[9], tl[3];
    const int bn  = blockIdx.x;
    const int tid = threadIdx.x;
    const float* proj = g_proj + bn*PROJ_W;

    if (tid < HH) { qq_sh[tid] = 0.f; kk_sh[tid] = 0.f; }
    if (tid < 9)  Rl[tid] = R[bn*9 + tid];
    if (tid < 3)  tl[tid] = t[bn*3 + tid];
    __syncthreads();

    for (int i = tid; i < HC; i += 128) {
        g_q[bn*HC + i] = proj[i];
        g_k[bn*HC + i] = proj[192 + i];
        g_v[bn*HC + i] = proj[384 + i];
    }
    if (tid < 96) {
        const int which = tid / 48;       // 0: qp, 1: kp
        const int pt    = tid % 48;       // h*PQ + p
        const int off   = which ? 720 : 576;
        const float px = proj[off + pt*3], py = proj[off + pt*3 + 1], pz = proj[off + pt*3 + 2];
        const float gx = Rl[0]*px + Rl[1]*py + Rl[2]*pz + tl[0];
        const float gy = Rl[3]*px + Rl[4]*py + Rl[5]*pz + tl[1];
        const float gz = Rl[6]*px + Rl[7]*py + Rl[8]*pz + tl[2];
        float* dst = (which ? g_kp : g_qp) + bn*HPQ3 + pt*3;
        dst[0] = gx; dst[1] = gy; dst[2] = gz;
        atomicAdd((which ? kk_sh : qq_sh) + pt/PQn, gx*gx + gy*gy + gz*gz);
    }
    if (tid < 96) {
        const int pt = tid;
        const float px = proj[864 + pt*3], py = proj[864 + pt*3 + 1], pz = proj[864 + pt*3 + 2];
        float* dst = g_vp + bn*HPV3 + pt*3;
        dst[0] = Rl[0]*px + Rl[1]*py + Rl[2]*pz + tl[0];
        dst[1] = Rl[3]*px + Rl[4]*py + Rl[5]*pz + tl[1];
        dst[2] = Rl[6]*px + Rl[7]*py + Rl[8]*pz + tl[2];
    }
    __syncthreads();
    if (tid < HH) { g_qq[bn*HH + tid] = qq_sh[tid]; g_kk[bn*HH + tid] = kk_sh[tid]; }
}

// ---------------------------------------------------------------------------
// Kernel: fused bias + logits + softmax + (o, opt, norm, opair) -> g_cat.
// One block = 4 query rows, 512 threads. og_s aliases wbT (dead after ph 1a).
// ---------------------------------------------------------------------------
#define L_LOGITS 0                 /* 4*12*512 = 24576 */
#define L_WBT    24576             /* 12*128   =  1536 ; aliased by og_s */
#define L_QS     26112             /* 4*192    =   768 */
#define L_QPS    26880             /* 4*192    =   768 */
#define L_QQS    27648             /* 48 */
#define L_GM     27696             /* 12 */
#define L_RS     27708             /* 36 */
#define L_TS     27744             /* 12 */
#define ATTN_SMEM_FLOATS 27756
#define ATTN_SMEM_BYTES  (ATTN_SMEM_FLOATS*4)

__global__ __launch_bounds__(512, 2) void k_attn(
    const float* __restrict__ z, const float* __restrict__ Wb,
    const float* __restrict__ hw, const float* __restrict__ R,
    const float* __restrict__ t)
{
    extern __shared__ __align__(16) float sm[];
    float* logits = sm + L_LOGITS;
    float* wbT    = sm + L_WBT;
    float* og_s   = sm + L_WBT;      // alias: wbT dead after phase 1a
    float* q_s    = sm + L_QS;
    float* qp_s   = sm + L_QPS;
    float* qq_s   = sm + L_QQS;
    float* gm     = sm + L_GM;
    float* R_s    = sm + L_RS;
    float* t_s    = sm + L_TS;

    const int tid = threadIdx.x;
    const int blk = blockIdx.x;
    const int b   = blk >> 7;            // 128 blocks per batch
    const int i0  = (blk & 127) << 2;    // 4 query rows per block

    // ---- setup ----
    for (int idx = tid; idx < HH*ZC; idx += 512) {
        const int h = idx / ZC, zi = idx % ZC;
        wbT[h*ZC + zi] = Wb[zi*HH + h];
    }
    for (int idx = tid; idx < 4*HC; idx += 512) {
        const int il = idx / HC;
        q_s[idx] = g_q[(b*NN + i0 + il)*HC + (idx % HC)];
    }
    for (int idx = tid; idx < 4*HPQ3; idx += 512) {
        const int il = idx / HPQ3, r = idx % HPQ3;
        const int h = r / 12, d = r % 12;
        qp_s[il*192 + h*16 + d] = g_qp[(b*NN + i0 + il)*HPQ3 + r];
    }
    if (tid < 48) qq_s[tid] = g_qq[(b*NN + i0 + tid/12)*HH + tid%12];
    if (tid < HH) gm[tid]   = log1pf(expf(hw[tid]));          // softplus
    if (tid < 36) R_s[tid]  = R[(b*NN + i0 + tid/9)*9 + tid%9];
    if (tid < 12) t_s[tid]  = t[(b*NN + i0 + tid/3)*3 + tid%3];
    __syncthreads();

    const int j = tid;   // this thread's key index

    // ---- phase 1a: pair bias (z @ Wb), all 12 heads per thread ----
    for (int il = 0; il < 4; il++) {
        float acc[HH];
        #pragma unroll
        for (int h = 0; h < HH; h++) acc[h] = 0.f;
        const float4* zr = (const float4*)(z + ((b*NN + i0 + il)*NN + j)*ZC);
        #pragma unroll 4
        for (int c4 = 0; c4 < ZC/4; c4++) {
            const float4 zv = zr[c4];
            #pragma unroll
            for (int h = 0; h < HH; h++) {
                const float4 wv = *(const float4*)(wbT + h*ZC + c4*4);
                acc[h] += zv.x*wv.x + zv.y*wv.y + zv.z*wv.z + zv.w*wv.w;
            }
        }
        #pragma unroll
        for (int h = 0; h < HH; h++) logits[(il*HH + h)*NN + j] = acc[h];
    }

    // ---- phase 1b: scalar + point logits ----
    {
        const float4* kr  = (const float4*)(g_k  + (b*NN + j)*HC);
        const float4* kpr = (const float4*)(g_kp + (b*NN + j)*HPQ3);
        const float*  kkr = g_kk + (b*NN + j)*HH;
        for (int h = 0; h < HH; h++) {
            const float4 kv0 = kr[h*4+0], kv1 = kr[h*4+1], kv2 = kr[h*4+2], kv3 = kr[h*4+3];
            const float4 kp0 = kpr[h*3+0], kp1 = kpr[h*3+1], kp2 = kpr[h*3+2];
            const float  kkh = kkr[h];
            const float  gch = COEF * gm[h];
            #pragma unroll
            for (int il = 0; il < 4; il++) {
                const float4* qh  = (const float4*)(q_s  + il*192 + h*16);
                const float4* qph = (const float4*)(qp_s + il*192 + h*16);
                float sc = dot4(qh[0],kv0) + dot4(qh[1],kv1) + dot4(qh[2],kv2) + dot4(qh[3],kv3);
                float qk = dot4(qph[0],kp0) + dot4(qph[1],kp1) + dot4(qph[2],kp2);
                const float d2 = qq_s[il*HH + h] + kkh - 2.f*qk;
                const int   li = (il*HH + h)*NN + j;
                logits[li] = WLC*(sc*0.25f + logits[li]) - gch*d2;
            }
        }
    }
    __syncthreads();

    // ---- phase 2: softmax over j, one warp per (il,h) row ----
    {
        const int wid = tid >> 5, lane = tid & 31;
        for (int row = wid; row < 48; row += 16) {
            float* Lr = logits + row*NN;
            float m = -1e30f;
            for (int c = lane; c < NN; c += 32) m = fmaxf(m, Lr[c]);
            #pragma unroll
            for (int o = 16; o; o >>= 1) m = fmaxf(m, __shfl_xor_sync(0xffffffffu, m, o));
            float ssum = 0.f;
            for (int c = lane; c < NN; c += 32) { const float e = __expf(Lr[c] - m); Lr[c] = e; ssum += e; }
            #pragma unroll
            for (int o = 16; o; o >>= 1) ssum += __shfl_xor_sync(0xffffffffu, ssum, o);
            const float inv = 1.f / ssum;
            for (int c = lane; c < NN; c += 32) Lr[c] *= inv;
        }
    }
    __syncthreads();

    // ---- phase 3a: opair = a @ z  (thread = (il, z-col), float4 a loads) ----
    {
        const int il  = tid >> 7;
        const int col = tid & 127;
        float acc[HH];
        #pragma unroll
        for (int h = 0; h < HH; h++) acc[h] = 0.f;
        const float* zcol = z + (b*NN + i0 + il)*NN*ZC + col;
        const float* arow = logits + il*HH*NN;
        for (int jj = 0; jj < NN; jj += 4) {
            const float z0 = zcol[(jj+0)*ZC];
            const float z1 = zcol[(jj+1)*ZC];
            const float z2 = zcol[(jj+2)*ZC];
            const float z3 = zcol[(jj+3)*ZC];
            #pragma unroll
            for (int h = 0; h < HH; h++) {
                const float4 av = *(const float4*)(arow + h*NN + jj);
                acc[h] = fmaf(av.x, z0, fmaf(av.y, z1, fmaf(av.z, z2, fmaf(av.w, z3, acc[h]))));
            }
        }
        float* dst = g_cat + (b*NN + i0 + il)*CATW + 576 + col;
        #pragma unroll
        for (int h = 0; h < HH; h++) dst[h*ZC] = acc[h];
    }

    // ---- phase 3b: o = a @ v ----
    for (int idx = tid; idx < 4*HC; idx += 512) {
        const int il = idx / HC, hc = idx % HC, h = hc >> 4;
        const float4* arow = (const float4*)(logits + (il*HH + h)*NN);
        const float* vcol = g_v + b*NN*HC + hc;
        float a0 = 0.f, a1 = 0.f, a2 = 0.f, a3 = 0.f;
        for (int jj4 = 0; jj4 < NN/4; jj4++) {
            const float4 a4 = arow[jj4];
            a0 = fmaf(a4.x, vcol[(jj4*4+0)*HC], a0);
            a1 = fmaf(a4.y, vcol[(jj4*4+1)*HC], a1);
            a2 = fmaf(a4.z, vcol[(jj4*4+2)*HC], a2);
            a3 = fmaf(a4.w, vcol[(jj4*4+3)*HC], a3);
        }
        g_cat[(b*NN + i0 + il)*CATW + hc] = (a0+a1)+(a2+a3);
    }

    // ---- phase 3c: opt_global = a @ vp ----
    for (int idx = tid; idx < 4*HPV3; idx += 512) {
        const int il = idx / HPV3, d = idx % HPV3, h = d / 24;
        const float4* arow = (const float4*)(logits + (il*HH + h)*NN);
        const float* vcol = g_vp + b*NN*HPV3 + d;
        float a0 = 0.f, a1 = 0.f, a2 = 0.f, a3 = 0.f;
        for (int jj4 = 0; jj4 < NN/4; jj4++) {
            const float4 a4 = arow[jj4];
            a0 = fmaf(a4.x, vcol[(jj4*4+0)*HPV3], a0);
            a1 = fmaf(a4.y, vcol[(jj4*4+1)*HPV3], a1);
            a2 = fmaf(a4.z, vcol[(jj4*4+2)*HPV3], a2);
            a3 = fmaf(a4.w, vcol[(jj4*4+3)*HPV3], a3);
        }
        og_s[il*HPV3 + d] = (a0+a1)+(a2+a3);
    }
    __syncthreads();

    // ---- phase 3d: back to local frame (R^T (x - t)), + norms ----
    for (int idx = tid; idx < 4*96; idx += 512) {
        const int il = idx / 96, hp = idx % 96;  // hp = h*8 + p
        const float dx = og_s[il*HPV3 + hp*3 + 0] - t_s[il*3 + 0];
        const float dy = og_s[il*HPV3 + hp*3 + 1] - t_s[il*3 + 1];
        const float dz = og_s[il*HPV3 + hp*3 + 2] - t_s[il*3 + 2];
        const float* Rr = R_s + il*9;
        const float ox = Rr[0]*dx + Rr[3]*dy + Rr[6]*dz;
        const float oy = Rr[1]*dx + Rr[4]*dy + Rr[7]*dz;
        const float oz = Rr[2]*dx + Rr[5]*dy + Rr[8]*dz;
        float* cg = g_cat + (b*NN + i0 + il)*CATW;
        cg[192 + hp*3 + 0] = ox;
        cg[192 + hp*3 + 1] = oy;
        cg[192 + hp*3 + 2] = oz;
        cg[480 + hp] = sqrtf(ox*ox + oy*oy + oz*oz + 1e-8f);
    }
}

// ---------------------------------------------------------------------------
extern "C" void kernel_launch(void* const* d_in, const int* in_sizes, int n_in,
                              void* d_out, int out_size)
{
    const float* s    = (const float*)d_in[0];
    const float* z    = (const float*)d_in[1];
    const float* R    = (const float*)d_in[2];
    const float* t    = (const float*)d_in[3];
    const float* Wq   = (const float*)d_in[4];
    const float* Wk   = (const float*)d_in[5];
    const float* Wv   = (const float*)d_in[6];
    const float* Wqp  = (const float*)d_in[7];
    const float* Wkp  = (const float*)d_in[8];
    const float* Wvp  = (const float*)d_in[9];
    const float* Wb   = (const float*)d_in[10];
    const float* hw   = (const float*)d_in[11];
    const float* Wout = (const float*)d_in[12];
    float* out = (float*)d_out;

    cudaFuncSetAttribute(k_attn, cudaFuncAttributeMaxDynamicSharedMemorySize, ATTN_SMEM_BYTES);

    float* g_wcat_p;  cudaGetSymbolAddress((void**)&g_wcat_p, g_wcat);
    float* g_proj_p;  cudaGetSymbolAddress((void**)&g_proj_p, g_proj);
    float* g_cat_p;   cudaGetSymbolAddress((void**)&g_cat_p,  g_cat);

    // 1) pack weights, project: g_proj[1024,1152] = s[1024,384] @ g_wcat
    k_pack<<<(SS*PROJ_W)/256, 256>>>(Wq, Wk, Wv, Wqp, Wkp, Wvp);
    {
        dim3 grid(PROJ_W/64, (BB*NN)/64);
        k_gemm<64, 64, 4, 4><<<grid, 256>>>(s, SS, g_wcat_p, PROJ_W, g_proj_p, PROJ_W, SS);
    }
    k_projpost<<<BB*NN, 128>>>(R, t);

    // 2) attention + gather into g_cat
    k_attn<<<BB*(NN/4), 512, ATTN_SMEM_BYTES>>>(z, Wb, hw, R, t);

    // 3) out = g_cat[1024,2112] @ Wout[2112,384]
    {
        dim3 grid(SS/64, (BB*NN)/16);
        k_gemm<16, 64, 1, 4><<<grid, 256>>>(g_cat_p, CATW, Wout, SS, out, SS, CATW);
    }
}

// round 3
// speedup vs baseline: 1.5535x; 1.5535x over previous
#include <cuda_runtime.h>
#include <math.h>

#define BB 2
#define NN 512
#define SS 384
#define ZC 128
#define HH 12
#define CC 16
#define PQn 4
#define PVn 8
#define HC 192      /* H*C   */
#define HPQ3 144    /* H*PQ*3*/
#define HPV3 288    /* H*PV*3*/
#define CATW 2112   /* H*(C+4PV+Z) */
#define PROJ_W 1152

#define WLC  0.5773502691896258f     /* sqrt(1/3) */
#define COEF 0.06804138174397717f    /* wL*wC/2, wC=sqrt(2/(9*PQ)) */

__device__ __align__(16) float g_q [BB*NN*HC];
__device__ __align__(16) float g_k [BB*NN*HC];
__device__ __align__(16) float g_v [BB*NN*HC];
__device__ __align__(16) float g_qp[BB*NN*HPQ3];
__device__ __align__(16) float g_kp[BB*NN*HPQ3];
__device__ __align__(16) float g_vp[BB*NN*HPV3];
__device__ __align__(16) float g_qq[BB*NN*HH];
__device__ __align__(16) float g_kk[BB*NN*HH];
__device__ __align__(16) float g_cat[BB*NN*CATW];
__device__ __align__(16) float g_wcat[SS*PROJ_W];   // packed projection weights
__device__ __align__(16) float g_proj[BB*NN*PROJ_W];

__device__ __forceinline__ float dot4(float4 a, float4 b) {
    return a.x*b.x + a.y*b.y + a.z*b.z + a.w*b.w;
}

// ---------------------------------------------------------------------------
// Kernel 0: pack Wq|Wk|Wv|Wqp|Wkp|Wvp into g_wcat[384][1152]
// ---------------------------------------------------------------------------
__global__ __launch_bounds__(256) void k_pack(
    const float* __restrict__ Wq, const float* __restrict__ Wk, const float* __restrict__ Wv,
    const float* __restrict__ Wqp, const float* __restrict__ Wkp, const float* __restrict__ Wvp)
{
    const int idx = blockIdx.x*256 + threadIdx.x;
    const int si = idx / PROJ_W, col = idx % PROJ_W;
    float v;
    if      (col < 192) v = Wq [si*192 + col];
    else if (col < 384) v = Wk [si*192 + col - 192];
    else if (col < 576) v = Wv [si*192 + col - 384];
    else if (col < 720) v = Wqp[si*144 + col - 576];
    else if (col < 864) v = Wkp[si*144 + col - 720];
    else                v = Wvp[si*288 + col - 864];
    g_wcat[idx] = v;
}

// ---------------------------------------------------------------------------
// Generic tiled fp32 GEMM: C[M,N] = A[M,lda] @ B[K,ldb], 256 threads.
// BM x BN tile, BK=32, each thread TM x TN outputs. (BM/TM)*(BN/TN)==256.
// ---------------------------------------------------------------------------
template<int BM, int BN, int TM, int TN>
__global__ __launch_bounds__(256) void k_gemm(
    const float* __restrict__ A, int lda,
    const float* __restrict__ B, int ldb,
    float* __restrict__ C, int ldc, int K)
{
    constexpr int BK = 32;
    __shared__ float As[BK][BM + 1];
    __shared__ __align__(16) float Bs[BK][BN];
    const int tid = threadIdx.x;
    const int ncols = BN / TN;               // thread cols
    const int tr = tid / ncols;              // thread row
    const int tc = tid % ncols;              // thread col
    const int m0 = blockIdx.y * BM;
    const int n0 = blockIdx.x * BN;

    float acc[TM][TN];
    #pragma unroll
    for (int i = 0; i < TM; i++)
        #pragma unroll
        for (int j = 0; j < TN; j++) acc[i][j] = 0.f;

    for (int k0 = 0; k0 < K; k0 += BK) {
        #pragma unroll
        for (int r = 0; r < (BM*BK)/256; r++) {
            const int idx = tid + r*256;
            const int m = idx / BK, kk = idx % BK;
            As[kk][m] = A[(m0 + m)*lda + k0 + kk];
        }
        #pragma unroll
        for (int r = 0; r < (BN*BK)/256; r++) {
            const int idx = tid + r*256;
            const int kk = idx / BN, n = idx % BN;
            Bs[kk][n] = B[(k0 + kk)*ldb + n0 + n];
        }
        __syncthreads();
        #pragma unroll
        for (int kk = 0; kk < BK; kk++) {
            float a[TM];
            #pragma unroll
            for (int i = 0; i < TM; i++) a[i] = As[kk][tr*TM + i];
            const float4 b4 = *(const float4*)&Bs[kk][tc*TN];
            #pragma unroll
            for (int i = 0; i < TM; i++) {
                acc[i][0] = fmaf(a[i], b4.x, acc[i][0]);
                acc[i][1] = fmaf(a[i], b4.y, acc[i][1]);
                acc[i][2] = fmaf(a[i], b4.z, acc[i][2]);
                acc[i][3] = fmaf(a[i], b4.w, acc[i][3]);
            }
        }
        __syncthreads();
    }
    #pragma unroll
    for (int i = 0; i < TM; i++) {
        float4 v = make_float4(acc[i][0], acc[i][1], acc[i][2], acc[i][3]);
        *(float4*)&C[(m0 + tr*TM + i)*ldc + n0 + tc*TN] = v;
    }
}

// ---------------------------------------------------------------------------
// Kernel: post-projection epilogue. One block per (b,n) residue.
// ---------------------------------------------------------------------------
__global__ __launch_bounds__(128) void k_projpost(
    const float* __restrict__ R, const float* __restrict__ t)
{
    __shared__ float qq_sh[HH], kk_sh[HH];
    __shared__ float Rl[9], tl[3];
    const int bn  = blockIdx.x;
    const int tid = threadIdx.x;
    const float* proj = g_proj + bn*PROJ_W;

    if (tid < HH) { qq_sh[tid] = 0.f; kk_sh[tid] = 0.f; }
    if (tid < 9)  Rl[tid] = R[bn*9 + tid];
    if (tid < 3)  tl[tid] = t[bn*3 + tid];
    __syncthreads();

    for (int i = tid; i < HC; i += 128) {
        g_q[bn*HC + i] = proj[i];
        g_k[bn*HC + i] = proj[192 + i];
        g_v[bn*HC + i] = proj[384 + i];
    }
    if (tid < 96) {
        const int which = tid / 48;       // 0: qp, 1: kp
        const int pt    = tid % 48;       // h*PQ + p
        const int off   = which ? 720 : 576;
        const float px = proj[off + pt*3], py = proj[off + pt*3 + 1], pz = proj[off + pt*3 + 2];
        const float gx = Rl[0]*px + Rl[1]*py + Rl[2]*pz + tl[0];
        const float gy = Rl[3]*px + Rl[4]*py + Rl[5]*pz + tl[1];
        const float gz = Rl[6]*px + Rl[7]*py + Rl[8]*pz + tl[2];
        float* dst = (which ? g_kp : g_qp) + bn*HPQ3 + pt*3;
        dst[0] = gx; dst[1] = gy; dst[2] = gz;
        atomicAdd((which ? kk_sh : qq_sh) + pt/PQn, gx*gx + gy*gy + gz*gz);
    }
    if (tid < 96) {
        const int pt = tid;
        const float px = proj[864 + pt*3], py = proj[864 + pt*3 + 1], pz = proj[864 + pt*3 + 2];
        float* dst = g_vp + bn*HPV3 + pt*3;
        dst[0] = Rl[0]*px + Rl[1]*py + Rl[2]*pz + tl[0];
        dst[1] = Rl[3]*px + Rl[4]*py + Rl[5]*pz + tl[1];
        dst[2] = Rl[6]*px + Rl[7]*py + Rl[8]*pz + tl[2];
    }
    __syncthreads();
    if (tid < HH) { g_qq[bn*HH + tid] = qq_sh[tid]; g_kk[bn*HH + tid] = kk_sh[tid]; }
}

// ---------------------------------------------------------------------------
// Kernel: fused bias + logits + softmax + (o, opt, norm, opair) -> g_cat.
// One block = 4 query rows, 512 threads, occupancy 1 (full reg budget — the
// R2 occupancy-2 cap caused spills; do NOT re-add min-blocks).
// ---------------------------------------------------------------------------
#define L_LOGITS 0                 /* 4*12*512 = 24576 */
#define L_WBT    24576             /* 12*128   =  1536 ; aliased by og_s */
#define L_QS     26112             /* 4*192    =   768 */
#define L_QPS    26880             /* 4*192    =   768 */
#define L_QQS    27648             /* 48 */
#define L_GM     27696             /* 12 */
#define L_RS     27708             /* 36 */
#define L_TS     27744             /* 12 */
#define ATTN_SMEM_FLOATS 27756
#define ATTN_SMEM_BYTES  (ATTN_SMEM_FLOATS*4)

__global__ __launch_bounds__(512) void k_attn(
    const float* __restrict__ z, const float* __restrict__ Wb,
    const float* __restrict__ hw, const float* __restrict__ R,
    const float* __restrict__ t)
{
    extern __shared__ __align__(16) float sm[];
    float* logits = sm + L_LOGITS;
    float* wbT    = sm + L_WBT;
    float* og_s   = sm + L_WBT;      // alias: wbT dead after phase 1a
    float* q_s    = sm + L_QS;
    float* qp_s   = sm + L_QPS;
    float* qq_s   = sm + L_QQS;
    float* gm     = sm + L_GM;
    float* R_s    = sm + L_RS;
    float* t_s    = sm + L_TS;

    const int tid = threadIdx.x;
    const int blk = blockIdx.x;
    const int b   = blk >> 7;            // 128 blocks per batch
    const int i0  = (blk & 127) << 2;    // 4 query rows per block

    // ---- setup ----
    for (int idx = tid; idx < HH*ZC; idx += 512) {
        const int h = idx / ZC, zi = idx % ZC;
        wbT[h*ZC + zi] = Wb[zi*HH + h];
    }
    for (int idx = tid; idx < 4*HC; idx += 512) {
        const int il = idx / HC;
        q_s[idx] = g_q[(b*NN + i0 + il)*HC + (idx % HC)];
    }
    for (int idx = tid; idx < 4*HPQ3; idx += 512) {
        const int il = idx / HPQ3, r = idx % HPQ3;
        const int h = r / 12, d = r % 12;
        qp_s[il*192 + h*16 + d] = g_qp[(b*NN + i0 + il)*HPQ3 + r];
    }
    if (tid < 48) qq_s[tid] = g_qq[(b*NN + i0 + tid/12)*HH + tid%12];
    if (tid < HH) gm[tid]   = log1pf(expf(hw[tid]));          // softplus
    if (tid < 36) R_s[tid]  = R[(b*NN + i0 + tid/9)*9 + tid%9];
    if (tid < 12) t_s[tid]  = t[(b*NN + i0 + tid/3)*3 + tid%3];
    __syncthreads();

    const int j = tid;   // this thread's key index

    // ---- phase 1a: pair bias (z @ Wb), all 12 heads per thread ----
    for (int il = 0; il < 4; il++) {
        float acc[HH];
        #pragma unroll
        for (int h = 0; h < HH; h++) acc[h] = 0.f;
        const float4* zr = (const float4*)(z + ((b*NN + i0 + il)*NN + j)*ZC);
        #pragma unroll 4
        for (int c4 = 0; c4 < ZC/4; c4++) {
            const float4 zv = zr[c4];
            #pragma unroll
            for (int h = 0; h < HH; h++) {
                const float4 wv = *(const float4*)(wbT + h*ZC + c4*4);
                acc[h] += zv.x*wv.x + zv.y*wv.y + zv.z*wv.z + zv.w*wv.w;
            }
        }
        #pragma unroll
        for (int h = 0; h < HH; h++) logits[(il*HH + h)*NN + j] = acc[h];
    }

    // ---- phase 1b: scalar + point logits ----
    {
        const float4* kr  = (const float4*)(g_k  + (b*NN + j)*HC);
        const float4* kpr = (const float4*)(g_kp + (b*NN + j)*HPQ3);
        const float*  kkr = g_kk + (b*NN + j)*HH;
        for (int h = 0; h < HH; h++) {
            const float4 kv0 = kr[h*4+0], kv1 = kr[h*4+1], kv2 = kr[h*4+2], kv3 = kr[h*4+3];
            const float4 kp0 = kpr[h*3+0], kp1 = kpr[h*3+1], kp2 = kpr[h*3+2];
            const float  kkh = kkr[h];
            const float  gch = COEF * gm[h];
            #pragma unroll
            for (int il = 0; il < 4; il++) {
                const float4* qh  = (const float4*)(q_s  + il*192 + h*16);
                const float4* qph = (const float4*)(qp_s + il*192 + h*16);
                float sc = dot4(qh[0],kv0) + dot4(qh[1],kv1) + dot4(qh[2],kv2) + dot4(qh[3],kv3);
                float qk = dot4(qph[0],kp0) + dot4(qph[1],kp1) + dot4(qph[2],kp2);
                const float d2 = qq_s[il*HH + h] + kkh - 2.f*qk;
                const int   li = (il*HH + h)*NN + j;
                logits[li] = WLC*(sc*0.25f + logits[li]) - gch*d2;
            }
        }
    }
    __syncthreads();

    // ---- phase 2: softmax over j, one warp per (il,h) row ----
    {
        const int wid = tid >> 5, lane = tid & 31;
        for (int row = wid; row < 48; row += 16) {
            float* Lr = logits + row*NN;
            float m = -1e30f;
            for (int c = lane; c < NN; c += 32) m = fmaxf(m, Lr[c]);
            #pragma unroll
            for (int o = 16; o; o >>= 1) m = fmaxf(m, __shfl_xor_sync(0xffffffffu, m, o));
            float ssum = 0.f;
            for (int c = lane; c < NN; c += 32) { const float e = __expf(Lr[c] - m); Lr[c] = e; ssum += e; }
            #pragma unroll
            for (int o = 16; o; o >>= 1) ssum += __shfl_xor_sync(0xffffffffu, ssum, o);
            const float inv = 1.f / ssum;
            for (int c = lane; c < NN; c += 32) Lr[c] *= inv;
        }
    }
    __syncthreads();

    // ---- phase 3a: opair = a @ z  (thread = (il, z-col), float4 a loads) ----
    {
        const int il  = tid >> 7;
        const int col = tid & 127;
        float acc[HH];
        #pragma unroll
        for (int h = 0; h < HH; h++) acc[h] = 0.f;
        const float* zcol = z + (b*NN + i0 + il)*NN*ZC + col;
        const float* arow = logits + il*HH*NN;
        for (int jj = 0; jj < NN; jj += 4) {
            const float z0 = zcol[(jj+0)*ZC];
            const float z1 = zcol[(jj+1)*ZC];
            const float z2 = zcol[(jj+2)*ZC];
            const float z3 = zcol[(jj+3)*ZC];
            #pragma unroll
            for (int h = 0; h < HH; h++) {
                const float4 av = *(const float4*)(arow + h*NN + jj);
                acc[h] = fmaf(av.x, z0, fmaf(av.y, z1, fmaf(av.z, z2, fmaf(av.w, z3, acc[h]))));
            }
        }
        float* dst = g_cat + (b*NN + i0 + il)*CATW + 576 + col;
        #pragma unroll
        for (int h = 0; h < HH; h++) dst[h*ZC] = acc[h];
    }

    // ---- phase 3b: o = a @ v ----
    for (int idx = tid; idx < 4*HC; idx += 512) {
        const int il = idx / HC, hc = idx % HC, h = hc >> 4;
        const float4* arow = (const float4*)(logits + (il*HH + h)*NN);
        const float* vcol = g_v + b*NN*HC + hc;
        float a0 = 0.f, a1 = 0.f, a2 = 0.f, a3 = 0.f;
        for (int jj4 = 0; jj4 < NN/4; jj4++) {
            const float4 a4 = arow[jj4];
            a0 = fmaf(a4.x, vcol[(jj4*4+0)*HC], a0);
            a1 = fmaf(a4.y, vcol[(jj4*4+1)*HC], a1);
            a2 = fmaf(a4.z, vcol[(jj4*4+2)*HC], a2);
            a3 = fmaf(a4.w, vcol[(jj4*4+3)*HC], a3);
        }
        g_cat[(b*NN + i0 + il)*CATW + hc] = (a0+a1)+(a2+a3);
    }

    // ---- phase 3c: opt_global = a @ vp ----
    for (int idx = tid; idx < 4*HPV3; idx += 512) {
        const int il = idx / HPV3, d = idx % HPV3, h = d / 24;
        const float4* arow = (const float4*)(logits + (il*HH + h)*NN);
        const float* vcol = g_vp + b*NN*HPV3 + d;
        float a0 = 0.f, a1 = 0.f, a2 = 0.f, a3 = 0.f;
        for (int jj4 = 0; jj4 < NN/4; jj4++) {
            const float4 a4 = arow[jj4];
            a0 = fmaf(a4.x, vcol[(jj4*4+0)*HPV3], a0);
            a1 = fmaf(a4.y, vcol[(jj4*4+1)*HPV3], a1);
            a2 = fmaf(a4.z, vcol[(jj4*4+2)*HPV3], a2);
            a3 = fmaf(a4.w, vcol[(jj4*4+3)*HPV3], a3);
        }
        og_s[il*HPV3 + d] = (a0+a1)+(a2+a3);
    }
    __syncthreads();

    // ---- phase 3d: back to local frame (R^T (x - t)), + norms ----
    for (int idx = tid; idx < 4*96; idx += 512) {
        const int il = idx / 96, hp = idx % 96;  // hp = h*8 + p
        const float dx = og_s[il*HPV3 + hp*3 + 0] - t_s[il*3 + 0];
        const float dy = og_s[il*HPV3 + hp*3 + 1] - t_s[il*3 + 1];
        const float dz = og_s[il*HPV3 + hp*3 + 2] - t_s[il*3 + 2];
        const float* Rr = R_s + il*9;
        const float ox = Rr[0]*dx + Rr[3]*dy + Rr[6]*dz;
        const float oy = Rr[1]*dx + Rr[4]*dy + Rr[7]*dz;
        const float oz = Rr[2]*dx + Rr[5]*dy + Rr[8]*dz;
        float* cg = g_cat + (b*NN + i0 + il)*CATW;
        cg[192 + hp*3 + 0] = ox;
        cg[192 + hp*3 + 1] = oy;
        cg[192 + hp*3 + 2] = oz;
        cg[480 + hp] = sqrtf(ox*ox + oy*oy + oz*oz + 1e-8f);
    }
}

// ---------------------------------------------------------------------------
extern "C" void kernel_launch(void* const* d_in, const int* in_sizes, int n_in,
                              void* d_out, int out_size)
{
    const float* s    = (const float*)d_in[0];
    const float* z    = (const float*)d_in[1];
    const float* R    = (const float*)d_in[2];
    const float* t    = (const float*)d_in[3];
    const float* Wq   = (const float*)d_in[4];
    const float* Wk   = (const float*)d_in[5];
    const float* Wv   = (const float*)d_in[6];
    const float* Wqp  = (const float*)d_in[7];
    const float* Wkp  = (const float*)d_in[8];
    const float* Wvp  = (const float*)d_in[9];
    const float* Wb   = (const float*)d_in[10];
    const float* hw   = (const float*)d_in[11];
    const float* Wout = (const float*)d_in[12];
    float* out = (float*)d_out;

    cudaFuncSetAttribute(k_attn, cudaFuncAttributeMaxDynamicSharedMemorySize, ATTN_SMEM_BYTES);

    float* g_wcat_p;  cudaGetSymbolAddress((void**)&g_wcat_p, g_wcat);
    float* g_proj_p;  cudaGetSymbolAddress((void**)&g_proj_p, g_proj);
    float* g_cat_p;   cudaGetSymbolAddress((void**)&g_cat_p,  g_cat);

    // 1) pack weights, project: g_proj[1024,1152] = s[1024,384] @ g_wcat
    k_pack<<<(SS*PROJ_W)/256, 256>>>(Wq, Wk, Wv, Wqp, Wkp, Wvp);
    {
        dim3 grid(PROJ_W/64, (BB*NN)/64);
        k_gemm<64, 64, 4, 4><<<grid, 256>>>(s, SS, g_wcat_p, PROJ_W, g_proj_p, PROJ_W, SS);
    }
    k_projpost<<<BB*NN, 128>>>(R, t);

    // 2) attention + gather into g_cat
    k_attn<<<BB*(NN/4), 512, ATTN_SMEM_BYTES>>>(z, Wb, hw, R, t);

    // 3) out = g_cat[1024,2112] @ Wout[2112,384]  (32x64 tile, TM=2: 8 FMA/kk)
    {
        dim3 grid(SS/64, (BB*NN)/32);
        k_gemm<32, 64, 2, 4><<<grid, 256>>>(g_cat_p, CATW, Wout, SS, out, SS, CATW);
    }
}